// round 10
// baseline (speedup 1.0000x reference)
#include <cuda_runtime.h>
#include <cstdint>

// x: [32, 512, 56, 56] fp32, chunks of 8 batches (51.4 MB, L2-resident).
// 5 launches, no tiny kernels:
//   R0  : reduce chunk0; last block per batch computes excitation in-place.
//   SA_c: scale chunk c (L2 reads + DRAM writes) + reduce-accumulate chunk c+1
//         (DRAM reads -> prime L2); last block per batch -> excitation c+1.
// DRAM total: 410 MB vs 616 MB.

#define C            512
#define CR           32
#define SPATIAL4     784                       // f4 per slice
#define SEGS_SLICE   196                       // 4-f4 segments per slice
#define CHUNK_B      8
#define NCHUNK       4
#define CHUNK_SLICES 4096
#define CHUNK_F4     (CHUNK_SLICES * SPATIAL4) // 3,211,264
#define NBLK         3136                      // CHUNK_F4 / 1024
#define BLKS_PER_BATCH_SA 392                  // 401408 f4 / 1024
#define BLKS_PER_BATCH_R0 512                  // slices per batch

__device__ float d_sq[32 * C];                 // RAW sums
__device__ float d_e[32 * C];
__device__ unsigned int g_cnt[32];             // per-batch completion counters

// ---------------------------------------------------------------------------
// Excitation for one batch, run by ONE block (any size >= 128, mult of 32).
// Reads raw sums via __ldcg (atomics live in L2), zeroes them for next replay.
// ---------------------------------------------------------------------------
__device__ __forceinline__ void excite_batch(
    int gb,
    const float* __restrict__ w1, const float* __restrict__ b1,
    const float* __restrict__ w2, const float* __restrict__ b2,
    float* sq, float* hid)                      // smem: 512 + 32
{
    const int tid    = threadIdx.x;
    const int nthr   = blockDim.x;
    const int nwarps = nthr >> 5;
    const int wid    = tid >> 5;
    const int lane   = tid & 31;

    for (int i = tid; i < C; i += nthr)
        sq[i] = __ldcg(&d_sq[gb * C + i]) * (1.0f / 3136.0f);
    __syncthreads();
    for (int i = tid; i < C; i += nthr)
        d_sq[gb * C + i] = 0.0f;               // replay-safe reset

    for (int u = wid; u < CR; u += nwarps) {
        const float* __restrict__ wrow = w1 + (size_t)u * C;
        float acc = 0.0f;
        #pragma unroll
        for (int k = 0; k < 16; ++k) {
            const int idx = lane + 32 * k;
            acc = fmaf(sq[idx], __ldg(&wrow[idx]), acc);
        }
        #pragma unroll
        for (int off = 16; off > 0; off >>= 1)
            acc += __shfl_down_sync(0xFFFFFFFFu, acc, off);
        if (lane == 0) hid[u] = fmaxf(acc + __ldg(&b1[u]), 0.0f);
    }
    __syncthreads();

    for (int c = tid; c < C; c += nthr) {
        float acc = __ldg(&b2[c]);
        const float* __restrict__ w2r = w2 + (size_t)c * CR;
        #pragma unroll
        for (int j = 0; j < CR; ++j)
            acc = fmaf(hid[j], __ldg(&w2r[j]), acc);
        d_e[gb * C + c] = 1.0f / (1.0f + __expf(-acc));
    }
}

// ---------------------------------------------------------------------------
// R0: one block per slice of chunk 0 (R1 shape, 6.28 TB/s proven).
// Last block of each batch computes the batch's excitation.
// ---------------------------------------------------------------------------
__global__ __launch_bounds__(128) void se_reduce0(
    const float* __restrict__ x,
    const float* __restrict__ w1, const float* __restrict__ b1,
    const float* __restrict__ w2, const float* __restrict__ b2)
{
    const int s  = blockIdx.x;                  // slice in chunk 0
    const int gb = s >> 9;                      // batch 0..7
    const float4* __restrict__ p =
        reinterpret_cast<const float4*>(x) + (size_t)s * SPATIAL4;

    float acc = 0.0f;
    #pragma unroll
    for (int i = threadIdx.x; i < SPATIAL4; i += 128) {
        float4 v = p[i];
        acc += (v.x + v.y) + (v.z + v.w);
    }
    #pragma unroll
    for (int off = 16; off > 0; off >>= 1)
        acc += __shfl_down_sync(0xFFFFFFFFu, acc, off);

    __shared__ float ws[4];
    __shared__ float sq_s[C];
    __shared__ float hid_s[CR];
    __shared__ bool  is_last;

    const int lane = threadIdx.x & 31;
    if (lane == 0) ws[threadIdx.x >> 5] = acc;
    __syncthreads();

    if (threadIdx.x == 0) {
        d_sq[s] = ws[0] + ws[1] + ws[2] + ws[3];
        __threadfence();
        is_last = (atomicAdd(&g_cnt[gb], 1u) == BLKS_PER_BATCH_R0 - 1u);
    }
    __syncthreads();

    if (is_last) {
        excite_batch(gb, w1, b1, w2, b2, sq_s, hid_s);
        __syncthreads();
        if (threadIdx.x == 0) atomicExch(&g_cnt[gb], 0u);
    }
}

// ---------------------------------------------------------------------------
// SA: scale chunk sc (4 consecutive f4/thread, one e lookup, __ldcs/__stcs)
// + if rc>=0, reduce-accumulate chunk rc (default loads prime L2, segmented
// warp reduction, <=2 atomicAdds/warp). Last block of each rc-batch computes
// that batch's excitation in-place.
// ---------------------------------------------------------------------------
__global__ __launch_bounds__(256) void se_scale_accum(
    const float* __restrict__ x,
    float* __restrict__ out,
    const float* __restrict__ w1, const float* __restrict__ b1,
    const float* __restrict__ w2, const float* __restrict__ b2,
    int sc, int rc)
{
    const int seg  = blockIdx.x * 256 + threadIdx.x;
    const int lane = threadIdx.x & 31;
    const int bc   = seg / SEGS_SLICE;                 // slice within chunk

    const float4* __restrict__ x4 = reinterpret_cast<const float4*>(x);
    float4*       __restrict__ o4 = reinterpret_cast<float4*>(out);

    const unsigned int base_s =
        (unsigned int)sc * CHUNK_F4 + (unsigned int)seg * 4u;

    float4 vs[4];
    #pragma unroll
    for (int j = 0; j < 4; ++j)
        vs[j] = __ldcs(x4 + base_s + j);

    float4 vr[4];
    if (rc >= 0) {
        const unsigned int base_r =
            (unsigned int)rc * CHUNK_F4 + (unsigned int)seg * 4u;
        #pragma unroll
        for (int j = 0; j < 4; ++j)
            vr[j] = x4[base_r + j];                    // default: keep in L2
    }

    const float e = __ldg(&d_e[sc * CHUNK_SLICES + bc]);
    #pragma unroll
    for (int j = 0; j < 4; ++j) {
        float4 r = vs[j];
        r.x *= e; r.y *= e; r.z *= e; r.w *= e;
        __stcs(o4 + base_s + j, r);
    }

    if (rc >= 0) {
        float s = 0.0f;
        #pragma unroll
        for (int j = 0; j < 4; ++j)
            s += (vr[j].x + vr[j].y) + (vr[j].z + vr[j].w);

        // head-segmented warp reduction keyed by slice id
        int key = bc;
        #pragma unroll
        for (int off = 16; off > 0; off >>= 1) {
            const float v2 = __shfl_down_sync(0xFFFFFFFFu, s, off);
            const int   k2 = __shfl_down_sync(0xFFFFFFFFu, key, off);
            if (lane + off < 32 && k2 == key) s += v2;
        }
        const int keyprev = __shfl_up_sync(0xFFFFFFFFu, key, 1);
        if (lane == 0 || keyprev != key)
            atomicAdd(&d_sq[rc * CHUNK_SLICES + bc], s);

        // ---- last-block-per-batch -> excitation ----
        __shared__ bool  is_last;
        __shared__ float sq_s[C];
        __shared__ float hid_s[CR];
        const int lb = blockIdx.x / BLKS_PER_BATCH_SA;  // local batch 0..7
        const int gb = rc * CHUNK_B + lb;
        __syncthreads();
        if (threadIdx.x == 0) {
            __threadfence();
            is_last = (atomicAdd(&g_cnt[gb], 1u) == BLKS_PER_BATCH_SA - 1u);
        }
        __syncthreads();
        if (is_last) {
            excite_batch(gb, w1, b1, w2, b2, sq_s, hid_s);
            __syncthreads();
            if (threadIdx.x == 0) atomicExch(&g_cnt[gb], 0u);
        }
    }
}

// ---------------------------------------------------------------------------
extern "C" void kernel_launch(void* const* d_in, const int* in_sizes, int n_in,
                              void* d_out, int out_size) {
    const float* x  = (const float*)d_in[0];
    const float* w1 = (const float*)d_in[1];
    const float* b1 = (const float*)d_in[2];
    const float* w2 = (const float*)d_in[3];
    const float* b2 = (const float*)d_in[4];
    float* out = (float*)d_out;

    se_reduce0<<<CHUNK_SLICES, 128>>>(x, w1, b1, w2, b2);
    for (int c = 0; c < NCHUNK; ++c) {
        const int rc = (c + 1 < NCHUNK) ? c + 1 : -1;
        se_scale_accum<<<NBLK, 256>>>(x, out, w1, b1, w2, b2, c, rc);
    }
}

// round 11
// speedup vs baseline: 1.4415x; 1.4415x over previous
#include <cuda_runtime.h>
#include <cstdint>

// x: [32, 512, 56, 56] fp32, chunks of 8 batches (51.4 MB, L2-resident).
// Pipeline (9 launches):
//   R0          : reduce chunk0 -> raw sums (R1 shape, 6.28 TB/s proven)
//   X(c)        : excitation for chunk c, 128 blocks (low-grid-throttle safe)
//   SA(c, c+1)  : scale chunk c (L2 reads + DRAM writes, coalesced R2 shape)
//                 + reduce-accumulate chunk c+1 (DRAM reads -> prime L2)
//                 + zero chunk c's raw sums (replay-safe)
// DRAM total: 410 MB vs 616 MB unchunked.

#define C            512
#define CR           32
#define SPATIAL4     784                       // f4 per slice
#define CHUNK_B      8
#define NCHUNK       4
#define CHUNK_SLICES 4096
#define CHUNK_F4     (CHUNK_SLICES * SPATIAL4) // 3,211,264
#define NBLK         3136                      // CHUNK_F4 / 1024

__device__ float d_sq[32 * C];                 // RAW sums (atomic-accumulated)
__device__ float d_e[32 * C];

// ---------------------------------------------------------------------------
// R0: one block per slice of chunk 0. Overwrites raw sums (no accumulation).
// ---------------------------------------------------------------------------
__global__ __launch_bounds__(128) void se_reduce0(const float* __restrict__ x)
{
    const int s = blockIdx.x;
    const float4* __restrict__ p =
        reinterpret_cast<const float4*>(x) + (size_t)s * SPATIAL4;

    float acc = 0.0f;
    #pragma unroll
    for (int i = threadIdx.x; i < SPATIAL4; i += 128) {
        float4 v = p[i];
        acc += (v.x + v.y) + (v.z + v.w);
    }
    #pragma unroll
    for (int off = 16; off > 0; off >>= 1)
        acc += __shfl_down_sync(0xFFFFFFFFu, acc, off);

    __shared__ float ws[4];
    const int lane = threadIdx.x & 31;
    if (lane == 0) ws[threadIdx.x >> 5] = acc;
    __syncthreads();
    if (threadIdx.x == 0)
        d_sq[s] = ws[0] + ws[1] + ws[2] + ws[3];
}

// ---------------------------------------------------------------------------
// X: excitation for one chunk. 128 blocks = 8 batches x 16 groups of 32
// channels. FC1 recomputed per block (trivial); FC2 on threads 0..31.
// ---------------------------------------------------------------------------
__global__ __launch_bounds__(128) void se_excite(
    const float* __restrict__ w1, const float* __restrict__ b1,
    const float* __restrict__ w2, const float* __restrict__ b2,
    int batch0)
{
    const int b    = batch0 + (blockIdx.x >> 4);
    const int grp  = blockIdx.x & 15;
    const int tid  = threadIdx.x;
    const int lane = tid & 31;
    const int wid  = tid >> 5;                  // 4 warps

    __shared__ float sq[C];
    __shared__ float hid[CR];

    for (int i = tid; i < C; i += 128)
        sq[i] = __ldcg(&d_sq[b * C + i]) * (1.0f / 3136.0f);
    __syncthreads();

    for (int u = wid; u < CR; u += 4) {
        const float* __restrict__ wrow = w1 + (size_t)u * C;
        float acc = 0.0f;
        #pragma unroll
        for (int k = 0; k < 16; ++k) {
            const int idx = lane + 32 * k;
            acc = fmaf(sq[idx], __ldg(&wrow[idx]), acc);
        }
        #pragma unroll
        for (int off = 16; off > 0; off >>= 1)
            acc += __shfl_down_sync(0xFFFFFFFFu, acc, off);
        if (lane == 0) hid[u] = fmaxf(acc + __ldg(&b1[u]), 0.0f);
    }
    __syncthreads();

    if (tid < 32) {
        const int c = grp * 32 + tid;
        float acc = __ldg(&b2[c]);
        const float* __restrict__ w2r = w2 + (size_t)c * CR;
        #pragma unroll
        for (int j = 0; j < CR; ++j)
            acc = fmaf(hid[j], __ldg(&w2r[j]), acc);
        d_e[b * C + c] = 1.0f / (1.0f + __expf(-acc));
    }
}

// ---------------------------------------------------------------------------
// SA: fully coalesced (R2 stride-256 interleave) scale of chunk sc +
// reduce-accumulate of chunk rc. Blocks 0..15 additionally zero chunk sc's
// raw sums (already consumed by its excite; launch boundary orders this).
// ---------------------------------------------------------------------------
__global__ __launch_bounds__(256) void se_scale_accum(
    const float* __restrict__ x,
    float* __restrict__ out,
    int sc, int rc)
{
    const unsigned int i0 =
        blockIdx.x * 1024u + threadIdx.x;          // f4 index within chunk
    const int lane = threadIdx.x & 31;

    const float4* __restrict__ x4 = reinterpret_cast<const float4*>(x);
    float4*       __restrict__ o4 = reinterpret_cast<float4*>(out);

    const unsigned int base_s = (unsigned int)sc * CHUNK_F4 + i0;

    // replay-safe zeroing of chunk sc's raw sums
    if (blockIdx.x < 16)
        d_sq[sc * CHUNK_SLICES + blockIdx.x * 256 + threadIdx.x] = 0.0f;

    // batched coalesced loads: 4 scale f4 (+4 reduce f4) in flight
    float4 vs[4];
    #pragma unroll
    for (int j = 0; j < 4; ++j)
        vs[j] = __ldcs(x4 + base_s + j * 256u);

    float sred[4];
    unsigned int base_r = 0;
    if (rc >= 0) {
        base_r = (unsigned int)rc * CHUNK_F4 + i0;
        #pragma unroll
        for (int j = 0; j < 4; ++j) {
            const float4 v = x4[base_r + j * 256u];   // default: keep in L2
            sred[j] = (v.x + v.y) + (v.z + v.w);      // consume immediately
        }
    }

    // scale + store (coalesced)
    #pragma unroll
    for (int j = 0; j < 4; ++j) {
        const float e = __ldg(&d_e[(base_s + j * 256u) / 784u]);
        float4 r = vs[j];
        r.x *= e; r.y *= e; r.z *= e; r.w *= e;
        __stcs(o4 + base_s + j * 256u, r);
    }

    // accumulate reduce sums: per-j head-segmented warp reduction
    if (rc >= 0) {
        #pragma unroll
        for (int j = 0; j < 4; ++j) {
            float s  = sred[j];
            int  key = (int)((base_r + j * 256u) / 784u);  // global slice id
            #pragma unroll
            for (int off = 16; off > 0; off >>= 1) {
                const float v2 = __shfl_down_sync(0xFFFFFFFFu, s, off);
                const int   k2 = __shfl_down_sync(0xFFFFFFFFu, key, off);
                if (lane + off < 32 && k2 == key) s += v2;
            }
            const int keyprev = __shfl_up_sync(0xFFFFFFFFu, key, 1);
            if (lane == 0 || keyprev != key)
                atomicAdd(&d_sq[key], s);
        }
    }
}

// ---------------------------------------------------------------------------
extern "C" void kernel_launch(void* const* d_in, const int* in_sizes, int n_in,
                              void* d_out, int out_size) {
    const float* x  = (const float*)d_in[0];
    const float* w1 = (const float*)d_in[1];
    const float* b1 = (const float*)d_in[2];
    const float* w2 = (const float*)d_in[3];
    const float* b2 = (const float*)d_in[4];
    float* out = (float*)d_out;

    se_reduce0<<<CHUNK_SLICES, 128>>>(x);
    for (int c = 0; c < NCHUNK; ++c) {
        se_excite<<<CHUNK_B * 16, 128>>>(w1, b1, w2, b2, c * CHUNK_B);
        const int rc = (c + 1 < NCHUNK) ? c + 1 : -1;
        se_scale_accum<<<NBLK, 256>>>(x, out, c, rc);
    }
}